// round 14
// baseline (speedup 1.0000x reference)
#include <cuda_runtime.h>
#include <cuda_bf16.h>
#include <stdint.h>

typedef unsigned long long U64;

// ======================= device scratch (no allocs rule) =====================
__device__ float          g_pre[4UL * 256 * 512 * 64];   // [t][gate][h][b] 128MiB
__device__ __nv_bfloat16  g_Ah[16384UL * 4096];          // gathered emb, hi split [m][k]
__device__ __nv_bfloat16  g_Al[16384UL * 4096];          // lo split
__device__ __nv_bfloat16  g_Bh[4UL * 512 * 4096];        // W_x [gate][h][k], hi
__device__ __nv_bfloat16  g_Bl[4UL * 512 * 4096];        // lo
__device__ __nv_bfloat16  g_hh[2][64 * 512];             // h state bf16 hi, ping-pong [b][h]
__device__ __nv_bfloat16  g_hl[2][64 * 512];             // h state bf16 lo
__device__ unsigned       g_bar;

// ======================= helpers ============================================
__device__ __forceinline__ float sig_(float x)  { return 1.0f / (1.0f + __expf(-x)); }
__device__ __forceinline__ float tanh_(float x) { return 2.0f * sig_(2.0f * x) - 1.0f; }

__device__ __forceinline__ uint32_t smem_u32(const void* p) {
    uint32_t a;
    asm("{ .reg .u64 t; cvta.to.shared.u64 t, %1; cvt.u32.u64 %0, t; }" : "=r"(a) : "l"(p));
    return a;
}
__device__ __forceinline__ void cpa16(uint32_t dst, const void* src) {
    asm volatile("cp.async.cg.shared.global [%0], [%1], 16;" :: "r"(dst), "l"(src));
}
#define CPA_COMMIT()  asm volatile("cp.async.commit_group;" ::: "memory")
#define CPA_WAIT0()   asm volatile("cp.async.wait_group 0;" ::: "memory")
#define CPA_WAIT1()   asm volatile("cp.async.wait_group 1;" ::: "memory")

__device__ __forceinline__ uint32_t swz(uint32_t o) { return o ^ ((o >> 3) & 0x70); }

__device__ __forceinline__ void ldsm4(uint32_t& r0, uint32_t& r1, uint32_t& r2, uint32_t& r3,
                                      uint32_t addr) {
    asm volatile("ldmatrix.sync.aligned.m8n8.x4.shared.b16 {%0,%1,%2,%3}, [%4];"
                 : "=r"(r0), "=r"(r1), "=r"(r2), "=r"(r3) : "r"(addr));
}
__device__ __forceinline__ void mma16816(float* c, const uint32_t* a, const uint32_t* b) {
    asm volatile("mma.sync.aligned.m16n8k16.row.col.f32.bf16.bf16.f32 "
                 "{%0,%1,%2,%3}, {%4,%5,%6,%7}, {%8,%9}, {%0,%1,%2,%3};"
                 : "+f"(c[0]), "+f"(c[1]), "+f"(c[2]), "+f"(c[3])
                 : "r"(a[0]), "r"(a[1]), "r"(a[2]), "r"(a[3]), "r"(b[0]), "r"(b[1]));
}
__device__ __forceinline__ void bar_arrive_release(unsigned* p) {
    asm volatile("red.release.gpu.add.u32 [%0], %1;" :: "l"(p), "r"(1u) : "memory");
}
__device__ __forceinline__ unsigned ld_acquire(unsigned* p) {
    unsigned v;
    asm volatile("ld.acquire.gpu.u32 %0, [%1];" : "=r"(v) : "l"(p) : "memory");
    return v;
}

// ======================= prep kernels =======================================
__global__ void prep_kernel() {
    if (blockIdx.x == 0 && threadIdx.x == 0) g_bar = 0u;
}

// W_x [4096 k][512 h] f32 -> [gate][512 h][4096 k] bf16 hi/lo (smem transpose)
__global__ void __launch_bounds__(256) prep_w_kernel(
    const float* __restrict__ Wf, const float* __restrict__ Wi,
    const float* __restrict__ Wg, const float* __restrict__ Wo)
{
    __shared__ float s[32][33];
    int bid = blockIdx.x;
    int kb = bid & 127, hb = (bid >> 7) & 15, g = bid >> 11;
    const float* __restrict__ W = (g == 0) ? Wf : (g == 1) ? Wi : (g == 2) ? Wg : Wo;
    int tid = threadIdx.x, c = tid & 31, r4 = (tid >> 5) * 4;
    int k0 = kb * 32, h0 = hb * 32;
#pragma unroll
    for (int r = 0; r < 4; ++r)
        s[r4 + r][c] = W[(size_t)(k0 + r4 + r) * 512 + h0 + c];
    __syncthreads();
#pragma unroll
    for (int r = 0; r < 4; ++r) {
        int hh = r4 + r;
        float v = s[c][hh];
        __nv_bfloat16 hi = __float2bfloat16(v);
        float lo = v - __bfloat162float(hi);
        size_t o = ((size_t)g * 512 + h0 + hh) * 4096 + k0 + c;
        g_Bh[o] = hi;
        g_Bl[o] = __float2bfloat16(lo);
    }
}

// gather emb rows per (t,b) -> g_Ah/g_Al [m=16384][k=4096] bf16 (u32 writes)
__global__ void __launch_bounds__(128) prep_a_kernel(
    const int* __restrict__ x, const float* __restrict__ emb)
{
    __shared__ int sTok[16];
    int m = blockIdx.x, t = m >> 6, b = m & 63;
    int tid = threadIdx.x;
    if (tid < 16) sTok[tid] = x[(b * 16 + tid) * 256 + t];
    __syncthreads();
    uint32_t* Ah32 = (uint32_t*)g_Ah;
    uint32_t* Al32 = (uint32_t*)g_Al;
    size_t base2 = (size_t)m * 2048;
#pragma unroll 4
    for (int p = 0; p < 16; ++p) {
        int tok = sTok[p];
        float2 v = (tok == 0) ? make_float2(0.f, 0.f)
                              : ((const float2*)emb)[(size_t)tok * 128 + tid];
        __nv_bfloat16 h0 = __float2bfloat16(v.x);
        __nv_bfloat16 h1 = __float2bfloat16(v.y);
        __nv_bfloat16 l0 = __float2bfloat16(v.x - __bfloat162float(h0));
        __nv_bfloat16 l1 = __float2bfloat16(v.y - __bfloat162float(h1));
        uint32_t hv = (uint32_t)__bfloat16_as_ushort(h0) |
                      ((uint32_t)__bfloat16_as_ushort(h1) << 16);
        uint32_t lv = (uint32_t)__bfloat16_as_ushort(l0) |
                      ((uint32_t)__bfloat16_as_ushort(l1) << 16);
        Ah32[base2 + p * 128 + tid] = hv;
        Al32[base2 + p * 128 + tid] = lv;
    }
}

// ======================= Phase 1: mma.sync bf16-split GEMM, 2 CTAs/SM ========
// (exactly as R13 — best known: tensor 83.5%, 1.63 ms)
#define GST_OFF(st) ((uint32_t)(st) * 49152u)
__global__ void __launch_bounds__(128, 2) gemm_kernel() {
    extern __shared__ char smem[];
    const uint32_t sb = smem_u32(smem);
    const int tid  = threadIdx.x;
    const int wid  = tid >> 5, lane = tid & 31;
    const int g    = blockIdx.x >> 2;
    const int n0   = (blockIdx.x & 3) * 128;
    const int m0   = blockIdx.y * 64;
    const int wm   = wid >> 1;
    const int wn   = wid & 1;

    const __nv_bfloat16* __restrict__ Ah = g_Ah + (size_t)m0 * 4096;
    const __nv_bfloat16* __restrict__ Al = g_Al + (size_t)m0 * 4096;
    const __nv_bfloat16* __restrict__ Bh = g_Bh + ((size_t)g * 512 + n0) * 4096;
    const __nv_bfloat16* __restrict__ Bl = g_Bl + ((size_t)g * 512 + n0) * 4096;

    auto load_chunk = [&](int st, int c) {
        const int k0 = c * 64;
        const uint32_t s0 = sb + GST_OFF(st);
#pragma unroll
        for (int j = 0; j < 4; ++j) {
            int a = tid + j * 128;
            int row = a >> 3, u = a & 7;
            uint32_t d = swz((uint32_t)(row * 128 + u * 16));
            const size_t go = (size_t)row * 4096 + k0 + u * 8;
            cpa16(s0 + d,         Ah + go);
            cpa16(s0 + 8192 + d,  Al + go);
        }
#pragma unroll
        for (int j = 0; j < 8; ++j) {
            int a = tid + j * 128;
            int row = a >> 3, u = a & 7;
            uint32_t d = swz((uint32_t)(row * 128 + u * 16));
            const size_t go = (size_t)row * 4096 + k0 + u * 8;
            cpa16(s0 + 16384 + d, Bh + go);
            cpa16(s0 + 32768 + d, Bl + go);
        }
        CPA_COMMIT();
    };

    float acc[2][8][4];
#pragma unroll
    for (int i = 0; i < 2; ++i)
#pragma unroll
        for (int j = 0; j < 8; ++j)
#pragma unroll
            for (int r = 0; r < 4; ++r) acc[i][j][r] = 0.0f;

    const uint32_t xr    = (uint32_t)(lane & 7) << 4;
    const uint32_t aRowB = (uint32_t)(wm * 32 + (lane & 15)) * 128;
    const uint32_t aUsel = (uint32_t)(lane >> 4);
    const uint32_t bRowB = (uint32_t)(wn * 64 + ((lane >> 4) << 3) + (lane & 7)) * 128;
    const uint32_t bUsel = (uint32_t)((lane >> 3) & 1);

    load_chunk(0, 0);

    for (int c = 0; c < 64; ++c) {
        if (c + 1 < 64) { load_chunk((c + 1) & 1, c + 1); CPA_WAIT1(); }
        else            { CPA_WAIT0(); }
        __syncthreads();

        const uint32_t s0 = sb + GST_OFF(c & 1);
        const uint32_t aBh = s0 + aRowB;
        const uint32_t aBl = s0 + 8192 + aRowB;
        const uint32_t bBh = s0 + 16384 + bRowB;
        const uint32_t bBl = s0 + 32768 + bRowB;

#pragma unroll
        for (int ks = 0; ks < 4; ++ks) {
            const uint32_t uA = ((uint32_t)(ks * 2) + aUsel) * 16 ^ xr;
            const uint32_t uB = ((uint32_t)(ks * 2) + bUsel) * 16 ^ xr;
            uint32_t aH[2][4], aL[2][4], bH[8][2], bL[8][2];
#pragma unroll
            for (int i = 0; i < 2; ++i) {
                ldsm4(aH[i][0], aH[i][1], aH[i][2], aH[i][3], aBh + i * 2048 + uA);
                ldsm4(aL[i][0], aL[i][1], aL[i][2], aL[i][3], aBl + i * 2048 + uA);
            }
#pragma unroll
            for (int jb = 0; jb < 4; ++jb) {
                ldsm4(bH[jb*2][0], bH[jb*2][1], bH[jb*2+1][0], bH[jb*2+1][1],
                      bBh + jb * 2048 + uB);
                ldsm4(bL[jb*2][0], bL[jb*2][1], bL[jb*2+1][0], bL[jb*2+1][1],
                      bBl + jb * 2048 + uB);
            }
#pragma unroll
            for (int i = 0; i < 2; ++i)
#pragma unroll
                for (int j = 0; j < 8; ++j) mma16816(acc[i][j], aH[i], bH[j]);
#pragma unroll
            for (int i = 0; i < 2; ++i)
#pragma unroll
                for (int j = 0; j < 8; ++j) mma16816(acc[i][j], aH[i], bL[j]);
#pragma unroll
            for (int i = 0; i < 2; ++i)
#pragma unroll
                for (int j = 0; j < 8; ++j) mma16816(acc[i][j], aL[i], bH[j]);
        }
        __syncthreads();
    }

    const int t  = blockIdx.y;
    const size_t tb = (size_t)(t * 4 + g) * 512;
#pragma unroll
    for (int i = 0; i < 2; ++i) {
        const int b0 = wm * 32 + i * 16 + (lane >> 2);
#pragma unroll
        for (int j = 0; j < 8; ++j) {
            const int h0 = n0 + wn * 64 + j * 8 + 2 * (lane & 3);
            float* p = g_pre + (tb + h0) * 64 + b0;
            p[0]      = acc[i][j][0];
            p[64]     = acc[i][j][1];
            p[8]      = acc[i][j][2];
            p[64 + 8] = acc[i][j][3];
        }
    }
}

__global__ void dummy_kernel() {}

// ======================= Phase 2: warp-autonomous tensor-core LSTM ===========
// grid = 128 CTAs (1/SM), block = 128 (4 warps). bf16 3-product (validated).
// NEW: zero block-wide syncs in the step loop. Warp w fills/consumes ONLY
// A-rows 16w..16w+15; poll + arrival are per-warp (goal = t*512).
__global__ void __launch_bounds__(128, 1) lstm_kernel(
    const float* __restrict__ Wfh, const float* __restrict__ Wih,
    const float* __restrict__ Wgh, const float* __restrict__ Woh,
    const float* __restrict__ Bf,  const float* __restrict__ Bi,
    const float* __restrict__ Bg,  const float* __restrict__ Bo,
    float* __restrict__ out)
{
    extern __shared__ char smem[];
    const uint32_t sb   = smem_u32(smem);
    const uint32_t sbAh = sb;
    const uint32_t sbAl = sb + 65536u;
    const uint32_t sbWh = sb + 131072u;
    const uint32_t sbWl = sb + 147456u;

    const int tid  = threadIdx.x;
    const int w    = tid >> 5, lane = tid & 31;
    const int hb   = blockIdx.x * 4;

    // ---- load W_h tile [16 c][512 k] bf16 hi/lo (staged at 0, relocated) ----
    for (int i = 0; i < 64; ++i) {
        int idx = i * 128 + tid;
        int c = idx >> 9, k = idx & 511;
        int gg = c & 3, j = c >> 2;
        const float* W = (gg == 0) ? Wfh : (gg == 1) ? Wih : (gg == 2) ? Wgh : Woh;
        float v = W[(size_t)k * 512 + hb + j];
        __nv_bfloat16 hi = __float2bfloat16(v);
        float lo = v - __bfloat162float(hi);
        uint32_t off = (uint32_t)c * 1024 + ((((uint32_t)k >> 3) ^ (uint32_t)(c & 7)) << 4)
                     + ((uint32_t)(k & 7) << 1);
        *(__nv_bfloat16*)(smem + (off))          = hi;
        *(__nv_bfloat16*)(smem + (off + 16384u)) = __float2bfloat16(lo);
    }
    __syncthreads();
    for (int i = tid; i < 8192; i += 128) {
        *(uint32_t*)(smem + 131072u + i * 4) = *(uint32_t*)(smem + i * 4);
    }
    __syncthreads();

    const int r    = lane >> 2;
    const int odd  = lane & 1;
    const int b    = 16 * w + r + (odd ? 8 : 0);
    const int j0   = (lane >> 1) & 1;
    const int h_0  = hb + j0;
    const int h_1  = hb + j0 + 2;

    const uint32_t aRow   = (uint32_t)(16 * w + (lane & 15));
    const uint32_t aBaseH = sbAh + aRow * 1024u;
    const uint32_t aBaseL = sbAl + aRow * 1024u;
    const uint32_t aXor   = aRow & 7u;
    const uint32_t aSel   = (uint32_t)(lane >> 4);
    const uint32_t bRow   = (uint32_t)(((lane >> 4) << 3) + (lane & 7));
    const uint32_t bBaseH = sbWh + bRow * 1024u;
    const uint32_t bBaseL = sbWl + bRow * 1024u;
    const uint32_t bXor   = bRow & 7u;
    const uint32_t bSel   = (uint32_t)((lane >> 3) & 1);

    const float bf0 = Bf[h_0], bi0 = Bi[h_0], bg0 = Bg[h_0], bo0 = Bo[h_0];
    const float bf1 = Bf[h_1], bi1 = Bi[h_1], bg1 = Bg[h_1], bo1 = Bo[h_1];

    float cst0 = 0.0f, cst1 = 0.0f;

    for (int t = 0; t < 256; ++t) {
        // pre-activation loads (GEMM-dependent only; issue before the poll)
        float pf0 = g_pre[((size_t)(t * 4 + 0) * 512 + h_0) * 64 + b];
        float pi0 = g_pre[((size_t)(t * 4 + 1) * 512 + h_0) * 64 + b];
        float pg0 = g_pre[((size_t)(t * 4 + 2) * 512 + h_0) * 64 + b];
        float po0 = g_pre[((size_t)(t * 4 + 3) * 512 + h_0) * 64 + b];
        float pf1 = g_pre[((size_t)(t * 4 + 0) * 512 + h_1) * 64 + b];
        float pi1 = g_pre[((size_t)(t * 4 + 1) * 512 + h_1) * 64 + b];
        float pg1 = g_pre[((size_t)(t * 4 + 2) * 512 + h_1) * 64 + b];
        float po1 = g_pre[((size_t)(t * 4 + 3) * 512 + h_1) * 64 + b];

        float c0[4] = {0.f, 0.f, 0.f, 0.f};
        float c1[4] = {0.f, 0.f, 0.f, 0.f};

        if (t > 0) {
            // per-warp acquire poll: 512 warp-arrivals per step
            if (lane == 0) {
                unsigned goal = (unsigned)t * 512u;
                while (ld_acquire(&g_bar) < goal) { }
            }
            __syncwarp();

            // fill OWN 16 rows (hi+lo), 2 k-half groups of 32 insts/lane
            const __nv_bfloat16* hh = g_hh[t & 1];
            const __nv_bfloat16* hl = g_hl[t & 1];
#pragma unroll
            for (int half = 0; half < 2; ++half) {
#pragma unroll
                for (int i = 0; i < 16; ++i) {
                    int idx = i * 32 + lane;                // 0..511
                    uint32_t rr = (uint32_t)(idx >> 5);     // 0..15
                    uint32_t u  = (uint32_t)(idx & 31) + (uint32_t)half * 32;
                    uint32_t R  = (uint32_t)(16 * w) + rr;
                    uint32_t d  = R * 1024u + ((u ^ (R & 7u)) << 4);
                    const size_t go = (size_t)R * 512 + u * 8;
                    cpa16(sbAh + d, hh + go);
                    cpa16(sbAl + d, hl + go);
                }
                CPA_COMMIT();
            }

#pragma unroll
            for (int half = 0; half < 2; ++half) {
                if (half == 0) { CPA_WAIT1(); } else { CPA_WAIT0(); }
                __syncwarp();
#pragma unroll
                for (int kk = 0; kk < 16; ++kk) {
                    const int kk16 = half * 16 + kk;
                    const uint32_t uA = (((uint32_t)(2 * kk16) + aSel) ^ aXor) << 4;
                    const uint32_t uB = (((uint32_t)(2 * kk16) + bSel) ^ bXor) << 4;
                    uint32_t aH[4], aL[4], bH[4], bL[4];
                    ldsm4(aH[0], aH[1], aH[2], aH[3], aBaseH + uA);
                    ldsm4(aL[0], aL[1], aL[2], aL[3], aBaseL + uA);
                    ldsm4(bH[0], bH[1], bH[2], bH[3], bBaseH + uB);
                    ldsm4(bL[0], bL[1], bL[2], bL[3], bBaseL + uB);
                    mma16816(c0, aH, bH);     mma16816(c1, aH, bH + 2);
                    mma16816(c0, aH, bL);     mma16816(c1, aH, bL + 2);
                    mma16816(c0, aL, bH);     mma16816(c1, aL, bH + 2);
                }
            }
        }

        // fragment exchange: lane pairs swap so each lane holds f,i,g,o
        float d0f, d0i, d0g, d0o, d1f, d1i, d1g, d1o;
        {
            float x0 = __shfl_xor_sync(0xffffffffu, c0[0], 1);
            float x1 = __shfl_xor_sync(0xffffffffu, c0[1], 1);
            float x2 = __shfl_xor_sync(0xffffffffu, c0[2], 1);
            float x3 = __shfl_xor_sync(0xffffffffu, c0[3], 1);
            if (!odd) { d0f = c0[0]; d0i = c0[1]; d0g = x0;   d0o = x1;   }
            else      { d0f = x2;    d0i = x3;    d0g = c0[2]; d0o = c0[3]; }
            float y0 = __shfl_xor_sync(0xffffffffu, c1[0], 1);
            float y1 = __shfl_xor_sync(0xffffffffu, c1[1], 1);
            float y2 = __shfl_xor_sync(0xffffffffu, c1[2], 1);
            float y3 = __shfl_xor_sync(0xffffffffu, c1[3], 1);
            if (!odd) { d1f = c1[0]; d1i = c1[1]; d1g = y0;   d1o = y1;   }
            else      { d1f = y2;    d1i = y3;    d1g = c1[2]; d1o = c1[3]; }
        }

        float f0 = sig_(pf0 + d0f + bf0);
        float i0 = sig_(pi0 + d0i + bi0);
        float gg0 = tanh_(pg0 + d0g + bg0);
        float o0 = sig_(po0 + d0o + bo0);
        cst0 = f0 * cst0 + i0 * gg0;
        float hv0 = o0 * tanh_(cst0);

        float f1 = sig_(pf1 + d1f + bf1);
        float i1 = sig_(pi1 + d1i + bi1);
        float gg1 = tanh_(pg1 + d1g + bg1);
        float o1 = sig_(po1 + d1o + bo1);
        cst1 = f1 * cst1 + i1 * gg1;
        float hv1 = o1 * tanh_(cst1);

        if (t == 255) {
            out[320 + b * 512 + h_0]         = hv0;
            out[320 + 32768 + b * 512 + h_0] = cst0;
            out[320 + b * 512 + h_1]         = hv1;
            out[320 + 32768 + b * 512 + h_1] = cst1;
        } else {
            __nv_bfloat16 h0h = __float2bfloat16(hv0);
            __nv_bfloat16 h0l = __float2bfloat16(hv0 - __bfloat162float(h0h));
            __nv_bfloat16 h1h = __float2bfloat16(hv1);
            __nv_bfloat16 h1l = __float2bfloat16(hv1 - __bfloat162float(h1h));
            const int nb = (t + 1) & 1;
            g_hh[nb][b * 512 + h_0] = h0h;  g_hl[nb][b * 512 + h_0] = h0l;
            g_hh[nb][b * 512 + h_1] = h1h;  g_hl[nb][b * 512 + h_1] = h1l;
            // warp-scope ordering, then per-warp release arrival
            __syncwarp();
            if (lane == 0) bar_arrive_release(&g_bar);
        }
    }
}

// ======================= Phase 3: output head ================================
__global__ void head_kernel(const float* __restrict__ Wl, const float* __restrict__ bl,
                            float* __restrict__ out)
{
    int b = blockIdx.x;
    int tid = threadIdx.x;
    int o = tid >> 5, lane = tid & 31;
    const float* hrow = out + 320 + b * 512;
    float s = 0.0f;
#pragma unroll 4
    for (int k = lane; k < 512; k += 32) s += hrow[k] * Wl[k * 5 + o];
#pragma unroll
    for (int m = 16; m; m >>= 1) s += __shfl_xor_sync(0xffffffffu, s, m);
    if (lane == 0) out[b * 5 + o] = s + bl[o];
}

// ======================= launch =============================================
extern "C" void kernel_launch(void* const* d_in, const int* in_sizes, int n_in,
                              void* d_out, int out_size)
{
    const int*   x   = (const int*)d_in[0];
    const float* emb = (const float*)d_in[1];
    const float* Wfx = (const float*)d_in[2];
    const float* Wfh = (const float*)d_in[3];
    const float* bf  = (const float*)d_in[4];
    const float* Wix = (const float*)d_in[5];
    const float* Wih = (const float*)d_in[6];
    const float* bi  = (const float*)d_in[7];
    const float* Wgx = (const float*)d_in[8];
    const float* Wgh = (const float*)d_in[9];
    const float* bg  = (const float*)d_in[10];
    const float* Wox = (const float*)d_in[11];
    const float* Woh = (const float*)d_in[12];
    const float* bo  = (const float*)d_in[13];
    const float* Wl  = (const float*)d_in[14];
    const float* bl  = (const float*)d_in[15];
    float* out = (float*)d_out;

    cudaFuncSetAttribute(gemm_kernel, cudaFuncAttributeMaxDynamicSharedMemorySize, 98304);
    cudaFuncSetAttribute(lstm_kernel, cudaFuncAttributeMaxDynamicSharedMemorySize, 163840);

    prep_kernel<<<1, 32>>>();
    prep_w_kernel<<<4 * 16 * 128, 256>>>(Wfx, Wix, Wgx, Wox);
    prep_a_kernel<<<16384, 128>>>(x, emb);
    gemm_kernel<<<dim3(16, 256), 128, 98304>>>();
    dummy_kernel<<<1, 32>>>();
    lstm_kernel<<<128, 128, 163840>>>(Wfh, Wih, Wgh, Woh, bf, bi, bg, bo, out);
    head_kernel<<<64, 160>>>(Wl, bl, out);
}

// round 16
// speedup vs baseline: 1.2506x; 1.2506x over previous
#include <cuda_runtime.h>
#include <cuda_bf16.h>
#include <stdint.h>

// ======================= device scratch (no allocs rule) =====================
__device__ float          g_pre[4UL * 256 * 512 * 64];   // [t][gate][h][b] 128MiB
__device__ __nv_bfloat16  g_Ah[16384UL * 4096];          // gathered emb, hi split [m][k]
__device__ __nv_bfloat16  g_Al[16384UL * 4096];          // lo split
__device__ __nv_bfloat16  g_Bh[4UL * 512 * 4096];        // W_x [gate][h][k], hi
__device__ __nv_bfloat16  g_Bl[4UL * 512 * 4096];        // lo
__device__ __nv_bfloat16  g_hh[2][64 * 512];             // h state bf16 hi, ping-pong [b][h]
__device__ __nv_bfloat16  g_hl[2][64 * 512];             // h state bf16 lo
__device__ unsigned       g_bar;
__device__ unsigned       g_done[256];                   // per-t gemm completion (16 each)

// ======================= helpers ============================================
__device__ __forceinline__ float sig_(float x)  { return 1.0f / (1.0f + __expf(-x)); }
__device__ __forceinline__ float tanh_(float x) { return 2.0f * sig_(2.0f * x) - 1.0f; }

__device__ __forceinline__ uint32_t smem_u32(const void* p) {
    uint32_t a;
    asm("{ .reg .u64 t; cvta.to.shared.u64 t, %1; cvt.u32.u64 %0, t; }" : "=r"(a) : "l"(p));
    return a;
}
__device__ __forceinline__ void cpa16(uint32_t dst, const void* src) {
    asm volatile("cp.async.cg.shared.global [%0], [%1], 16;" :: "r"(dst), "l"(src));
}
#define CPA_COMMIT()  asm volatile("cp.async.commit_group;" ::: "memory")
#define CPA_WAIT0()   asm volatile("cp.async.wait_group 0;" ::: "memory")
#define CPA_WAIT1()   asm volatile("cp.async.wait_group 1;" ::: "memory")

__device__ __forceinline__ uint32_t swz(uint32_t o) { return o ^ ((o >> 3) & 0x70); }

__device__ __forceinline__ void ldsm4(uint32_t& r0, uint32_t& r1, uint32_t& r2, uint32_t& r3,
                                      uint32_t addr) {
    asm volatile("ldmatrix.sync.aligned.m8n8.x4.shared.b16 {%0,%1,%2,%3}, [%4];"
                 : "=r"(r0), "=r"(r1), "=r"(r2), "=r"(r3) : "r"(addr));
}
__device__ __forceinline__ void mma16816(float* c, const uint32_t* a, const uint32_t* b) {
    asm volatile("mma.sync.aligned.m16n8k16.row.col.f32.bf16.bf16.f32 "
                 "{%0,%1,%2,%3}, {%4,%5,%6,%7}, {%8,%9}, {%0,%1,%2,%3};"
                 : "+f"(c[0]), "+f"(c[1]), "+f"(c[2]), "+f"(c[3])
                 : "r"(a[0]), "r"(a[1]), "r"(a[2]), "r"(a[3]), "r"(b[0]), "r"(b[1]));
}
__device__ __forceinline__ void bar_arrive_release(unsigned* p) {
    asm volatile("red.release.gpu.add.u32 [%0], %1;" :: "l"(p), "r"(1u) : "memory");
}
__device__ __forceinline__ unsigned ld_acquire(unsigned* p) {
    unsigned v;
    asm volatile("ld.acquire.gpu.u32 %0, [%1];" : "=r"(v) : "l"(p) : "memory");
    return v;
}

// ======================= prep kernels =======================================
__global__ void prep_kernel() {
    int i = threadIdx.x;
    if (i == 0) g_bar = 0u;
    if (i < 256) g_done[i] = 0u;
}

// W_x [4096 k][512 h] f32 -> [gate][512 h][4096 k] bf16 hi/lo (smem transpose)
__global__ void __launch_bounds__(256) prep_w_kernel(
    const float* __restrict__ Wf, const float* __restrict__ Wi,
    const float* __restrict__ Wg, const float* __restrict__ Wo)
{
    __shared__ float s[32][33];
    int bid = blockIdx.x;
    int kb = bid & 127, hb = (bid >> 7) & 15, g = bid >> 11;
    const float* __restrict__ W = (g == 0) ? Wf : (g == 1) ? Wi : (g == 2) ? Wg : Wo;
    int tid = threadIdx.x, c = tid & 31, r4 = (tid >> 5) * 4;
    int k0 = kb * 32, h0 = hb * 32;
#pragma unroll
    for (int r = 0; r < 4; ++r)
        s[r4 + r][c] = W[(size_t)(k0 + r4 + r) * 512 + h0 + c];
    __syncthreads();
#pragma unroll
    for (int r = 0; r < 4; ++r) {
        int hh = r4 + r;
        float v = s[c][hh];
        __nv_bfloat16 hi = __float2bfloat16(v);
        float lo = v - __bfloat162float(hi);
        size_t o = ((size_t)g * 512 + h0 + hh) * 4096 + k0 + c;
        g_Bh[o] = hi;
        g_Bl[o] = __float2bfloat16(lo);
    }
}

// gather emb rows per (t,b) -> g_Ah/g_Al [m=16384][k=4096] bf16 (u32 writes)
__global__ void __launch_bounds__(128) prep_a_kernel(
    const int* __restrict__ x, const float* __restrict__ emb)
{
    __shared__ int sTok[16];
    int m = blockIdx.x, t = m >> 6, b = m & 63;
    int tid = threadIdx.x;
    if (tid < 16) sTok[tid] = x[(b * 16 + tid) * 256 + t];
    __syncthreads();
    uint32_t* Ah32 = (uint32_t*)g_Ah;
    uint32_t* Al32 = (uint32_t*)g_Al;
    size_t base2 = (size_t)m * 2048;
#pragma unroll 4
    for (int p = 0; p < 16; ++p) {
        int tok = sTok[p];
        float2 v = (tok == 0) ? make_float2(0.f, 0.f)
                              : ((const float2*)emb)[(size_t)tok * 128 + tid];
        __nv_bfloat16 h0 = __float2bfloat16(v.x);
        __nv_bfloat16 h1 = __float2bfloat16(v.y);
        __nv_bfloat16 l0 = __float2bfloat16(v.x - __bfloat162float(h0));
        __nv_bfloat16 l1 = __float2bfloat16(v.y - __bfloat162float(h1));
        uint32_t hv = (uint32_t)__bfloat16_as_ushort(h0) |
                      ((uint32_t)__bfloat16_as_ushort(h1) << 16);
        uint32_t lv = (uint32_t)__bfloat16_as_ushort(l0) |
                      ((uint32_t)__bfloat16_as_ushort(l1) << 16);
        Ah32[base2 + p * 128 + tid] = hv;
        Al32[base2 + p * 128 + tid] = lv;
    }
}

// ======================= fused kernel: gemm producer + lstm consumer =========
// grid = 4224, block = 128, 96KB smem.
// bid 0..127: lstm role (one per SM, wave 1). bid 128..4223: gemm role.

// ---- gemm role: R13-validated 64m x 128n tile, 2-stage, + g_done release ----
#define GST_OFF(st) ((uint32_t)(st) * 49152u)
__device__ __forceinline__ void gemm_role(int bidp, char* smem) {
    const uint32_t sb = smem_u32(smem);
    const int tid  = threadIdx.x;
    const int wid  = tid >> 5, lane = tid & 31;
    const int q16  = bidp & 15;
    const int g    = q16 >> 2;
    const int n0   = (q16 & 3) * 128;
    const int t    = bidp >> 4;
    const int m0   = t * 64;
    const int wm   = wid >> 1;
    const int wn   = wid & 1;

    const __nv_bfloat16* __restrict__ Ah = g_Ah + (size_t)m0 * 4096;
    const __nv_bfloat16* __restrict__ Al = g_Al + (size_t)m0 * 4096;
    const __nv_bfloat16* __restrict__ Bh = g_Bh + ((size_t)g * 512 + n0) * 4096;
    const __nv_bfloat16* __restrict__ Bl = g_Bl + ((size_t)g * 512 + n0) * 4096;

    auto load_chunk = [&](int st, int c) {
        const int k0 = c * 64;
        const uint32_t s0 = sb + GST_OFF(st);
#pragma unroll
        for (int j = 0; j < 4; ++j) {
            int a = tid + j * 128;
            int row = a >> 3, u = a & 7;
            uint32_t d = swz((uint32_t)(row * 128 + u * 16));
            const size_t go = (size_t)row * 4096 + k0 + u * 8;
            cpa16(s0 + d,         Ah + go);
            cpa16(s0 + 8192 + d,  Al + go);
        }
#pragma unroll
        for (int j = 0; j < 8; ++j) {
            int a = tid + j * 128;
            int row = a >> 3, u = a & 7;
            uint32_t d = swz((uint32_t)(row * 128 + u * 16));
            const size_t go = (size_t)row * 4096 + k0 + u * 8;
            cpa16(s0 + 16384 + d, Bh + go);
            cpa16(s0 + 32768 + d, Bl + go);
        }
        CPA_COMMIT();
    };

    float acc[2][8][4];
#pragma unroll
    for (int i = 0; i < 2; ++i)
#pragma unroll
        for (int j = 0; j < 8; ++j)
#pragma unroll
            for (int r = 0; r < 4; ++r) acc[i][j][r] = 0.0f;

    const uint32_t xr    = (uint32_t)(lane & 7) << 4;
    const uint32_t aRowB = (uint32_t)(wm * 32 + (lane & 15)) * 128;
    const uint32_t aUsel = (uint32_t)(lane >> 4);
    const uint32_t bRowB = (uint32_t)(wn * 64 + ((lane >> 4) << 3) + (lane & 7)) * 128;
    const uint32_t bUsel = (uint32_t)((lane >> 3) & 1);

    load_chunk(0, 0);

    for (int c = 0; c < 64; ++c) {
        if (c + 1 < 64) { load_chunk((c + 1) & 1, c + 1); CPA_WAIT1(); }
        else            { CPA_WAIT0(); }
        __syncthreads();

        const uint32_t s0 = sb + GST_OFF(c & 1);
        const uint32_t aBh = s0 + aRowB;
        const uint32_t aBl = s0 + 8192 + aRowB;
        const uint32_t bBh = s0 + 16384 + bRowB;
        const uint32_t bBl = s0 + 32768 + bRowB;

#pragma unroll
        for (int ks = 0; ks < 4; ++ks) {
            const uint32_t uA = ((uint32_t)(ks * 2) + aUsel) * 16 ^ xr;
            const uint32_t uB = ((uint32_t)(ks * 2) + bUsel) * 16 ^ xr;
            uint32_t aH[2][4], aL[2][4], bH[8][2], bL[8][2];
#pragma unroll
            for (int i = 0; i < 2; ++i) {
                ldsm4(aH[i][0], aH[i][1], aH[i][2], aH[i][3], aBh + i * 2048 + uA);
                ldsm4(aL[i][0], aL[i][1], aL[i][2], aL[i][3], aBl + i * 2048 + uA);
            }
#pragma unroll
            for (int jb = 0; jb < 4; ++jb) {
                ldsm4(bH[jb*2][0], bH[jb*2][1], bH[jb*2+1][0], bH[jb*2+1][1],
                      bBh + jb * 2048 + uB);
                ldsm4(bL[jb*2][0], bL[jb*2][1], bL[jb*2+1][0], bL[jb*2+1][1],
                      bBl + jb * 2048 + uB);
            }
#pragma unroll
            for (int i = 0; i < 2; ++i)
#pragma unroll
                for (int j = 0; j < 8; ++j) mma16816(acc[i][j], aH[i], bH[j]);
#pragma unroll
            for (int i = 0; i < 2; ++i)
#pragma unroll
                for (int j = 0; j < 8; ++j) mma16816(acc[i][j], aH[i], bL[j]);
#pragma unroll
            for (int i = 0; i < 2; ++i)
#pragma unroll
                for (int j = 0; j < 8; ++j) mma16816(acc[i][j], aL[i], bH[j]);
        }
        __syncthreads();
    }

    const size_t tb = (size_t)(t * 4 + g) * 512;
#pragma unroll
    for (int i = 0; i < 2; ++i) {
        const int b0 = wm * 32 + i * 16 + (lane >> 2);
#pragma unroll
        for (int j = 0; j < 8; ++j) {
            const int h0 = n0 + wn * 64 + j * 8 + 2 * (lane & 3);
            float* p = g_pre + (tb + h0) * 64 + b0;
            p[0]      = acc[i][j][0];
            p[64]     = acc[i][j][1];
            p[8]      = acc[i][j][2];
            p[64 + 8] = acc[i][j][3];
        }
    }
    // publish: this t-tile is done (16 CTAs per t)
    __syncthreads();
    if (tid == 0) bar_arrive_release(&g_done[t]);
}

// ---- lstm role: R13 logic, h streamed through double-buffered 32KB quarters.
// smem: buf0 32KB (Ah 16K | Al 16K) | buf1 32KB | Wh 16KB | Wl 16KB = 96KB.
__device__ __forceinline__ void lstm_role(
    char* smem,
    const float* __restrict__ Wfh, const float* __restrict__ Wih,
    const float* __restrict__ Wgh, const float* __restrict__ Woh,
    const float* __restrict__ Bf,  const float* __restrict__ Bi,
    const float* __restrict__ Bg,  const float* __restrict__ Bo,
    float* __restrict__ out)
{
    const uint32_t sb   = smem_u32(smem);
    const uint32_t sbWh = sb + 65536u;
    const uint32_t sbWl = sb + 81920u;

    const int tid  = threadIdx.x;
    const int w    = tid >> 5, lane = tid & 31;
    const int hb   = blockIdx.x * 4;

    // W_h tile [16 c][512 k] bf16 hi/lo, written directly to its region
    for (int i = 0; i < 64; ++i) {
        int idx = i * 128 + tid;
        int c = idx >> 9, k = idx & 511;
        int gg = c & 3, j = c >> 2;
        const float* W = (gg == 0) ? Wfh : (gg == 1) ? Wih : (gg == 2) ? Wgh : Woh;
        float v = W[(size_t)k * 512 + hb + j];
        __nv_bfloat16 hi = __float2bfloat16(v);
        float lo = v - __bfloat162float(hi);
        uint32_t off = (uint32_t)c * 1024 + ((((uint32_t)k >> 3) ^ (uint32_t)(c & 7)) << 4)
                     + ((uint32_t)(k & 7) << 1);
        *(__nv_bfloat16*)(smem + 65536u + off) = hi;
        *(__nv_bfloat16*)(smem + 81920u + off) = __float2bfloat16(lo);
    }
    __syncthreads();

    const int r    = lane >> 2;
    const int odd  = lane & 1;
    const int b    = 16 * w + r + (odd ? 8 : 0);
    const int j0   = (lane >> 1) & 1;
    const int h_0  = hb + j0;
    const int h_1  = hb + j0 + 2;

    const uint32_t aRow   = (uint32_t)(16 * w + (lane & 15));
    const uint32_t aXor   = aRow & 7u;
    const uint32_t aSel   = (uint32_t)(lane >> 4);
    const uint32_t bRow   = (uint32_t)(((lane >> 4) << 3) + (lane & 7));
    const uint32_t bBaseH = sbWh + bRow * 1024u;
    const uint32_t bBaseL = sbWl + bRow * 1024u;
    const uint32_t bXor   = bRow & 7u;
    const uint32_t bSel   = (uint32_t)((lane >> 3) & 1);

    const float bf0 = Bf[h_0], bi0 = Bi[h_0], bg0 = Bg[h_0], bo0 = Bo[h_0];
    const float bf1 = Bf[h_1], bi1 = Bi[h_1], bg1 = Bg[h_1], bo1 = Bo[h_1];

    float cst0 = 0.0f, cst1 = 0.0f;

    for (int t = 0; t < 256; ++t) {
        // gate on producer (pre[t]) and on peers' h(t) stores
        if (tid == 0) {
            while (ld_acquire(&g_done[t]) < 16u) { }
            if (t > 0) {
                unsigned goal = (unsigned)t * 128u;
                while (ld_acquire(&g_bar) < goal) { }
            }
        }
        __syncthreads();

        // pre-activation loads (DRAM-latency; issue before fills)
        float pf0 = g_pre[((size_t)(t * 4 + 0) * 512 + h_0) * 64 + b];
        float pi0 = g_pre[((size_t)(t * 4 + 1) * 512 + h_0) * 64 + b];
        float pg0 = g_pre[((size_t)(t * 4 + 2) * 512 + h_0) * 64 + b];
        float po0 = g_pre[((size_t)(t * 4 + 3) * 512 + h_0) * 64 + b];
        float pf1 = g_pre[((size_t)(t * 4 + 0) * 512 + h_1) * 64 + b];
        float pi1 = g_pre[((size_t)(t * 4 + 1) * 512 + h_1) * 64 + b];
        float pg1 = g_pre[((size_t)(t * 4 + 2) * 512 + h_1) * 64 + b];
        float po1 = g_pre[((size_t)(t * 4 + 3) * 512 + h_1) * 64 + b];

        float c0[4] = {0.f, 0.f, 0.f, 0.f};
        float c1[4] = {0.f, 0.f, 0.f, 0.f};

        if (t > 0) {
            const __nv_bfloat16* hh = g_hh[t & 1];
            const __nv_bfloat16* hl = g_hl[t & 1];

            auto fill_q = [&](int st, int q) {
                const uint32_t s0 = sb + (uint32_t)st * 32768u;
#pragma unroll
                for (int i = 0; i < 8; ++i) {
                    int item = i * 128 + tid;            // 0..1023
                    int bb = item >> 4;                  // 0..63
                    int uu = item & 15;                  // 0..15
                    uint32_t d = (uint32_t)bb * 256u +
                                 ((((uint32_t)uu) ^ ((uint32_t)bb & 7u)) << 4);
                    const size_t go = (size_t)bb * 512 + q * 128 + uu * 8;
                    cpa16(s0 + d,          hh + go);
                    cpa16(s0 + 16384u + d, hl + go);
                }
                CPA_COMMIT();
            };

            fill_q(0, 0);
            fill_q(1, 1);
#pragma unroll
            for (int q = 0; q < 4; ++q) {
                if (q < 3) { CPA_WAIT1(); } else { CPA_WAIT0(); }
                __syncthreads();
                const uint32_t s0  = sb + (uint32_t)(q & 1) * 32768u;
                const uint32_t aBh = s0 + aRow * 256u;
                const uint32_t aBl = s0 + 16384u + aRow * 256u;
#pragma unroll
                for (int kkq = 0; kkq < 8; ++kkq) {
                    const int kk16 = q * 8 + kkq;
                    const uint32_t uA = (((uint32_t)(2 * kkq)  + aSel) ^ aXor) << 4;
                    const uint32_t uB = (((uint32_t)(2 * kk16) + bSel) ^ bXor) << 4;
                    uint32_t aH[4], aL[4], bH[4], bL[4];
                    ldsm4(aH[0], aH[1], aH[2], aH[3], aBh + uA);
                    ldsm4(aL[0], aL[1], aL[2], aL[3], aBl + uA);
                    ldsm4(bH[0], bH[1], bH[2], bH[3], bBaseH + uB);
                    ldsm4(bL[0], bL[1], bL[2], bL[3], bBaseL + uB);
                    mma16816(c0, aH, bH);     mma16816(c1, aH, bH + 2);
                    mma16816(c0, aH, bL);     mma16816(c1, aH, bL + 2);
                    mma16816(c0, aL, bH);     mma16816(c1, aL, bH + 2);
                }
                __syncthreads();
                if (q + 2 < 4) fill_q(q & 1, q + 2);
            }
        }

        // fragment exchange: lane pairs swap so each lane holds f,i,g,o
        float d0f, d0i, d0g, d0o, d1f, d1i, d1g, d1o;
        {
            float x0 = __shfl_xor_sync(0xffffffffu, c0[0], 1);
            float x1 = __shfl_xor_sync(0xffffffffu, c0[1], 1);
            float x2 = __shfl_xor_sync(0xffffffffu, c0[2], 1);
            float x3 = __shfl_xor_sync(0xffffffffu, c0[3], 1);
            if (!odd) { d0f = c0[0]; d0i = c0[1]; d0g = x0;   d0o = x1;   }
            else      { d0f = x2;    d0i = x3;    d0g = c0[2]; d0o = c0[3]; }
            float y0 = __shfl_xor_sync(0xffffffffu, c1[0], 1);
            float y1 = __shfl_xor_sync(0xffffffffu, c1[1], 1);
            float y2 = __shfl_xor_sync(0xffffffffu, c1[2], 1);
            float y3 = __shfl_xor_sync(0xffffffffu, c1[3], 1);
            if (!odd) { d1f = c1[0]; d1i = c1[1]; d1g = y0;   d1o = y1;   }
            else      { d1f = y2;    d1i = y3;    d1g = c1[2]; d1o = c1[3]; }
        }

        float f0 = sig_(pf0 + d0f + bf0);
        float i0 = sig_(pi0 + d0i + bi0);
        float gg0 = tanh_(pg0 + d0g + bg0);
        float o0 = sig_(po0 + d0o + bo0);
        cst0 = f0 * cst0 + i0 * gg0;
        float hv0 = o0 * tanh_(cst0);

        float f1 = sig_(pf1 + d1f + bf1);
        float i1 = sig_(pi1 + d1i + bi1);
        float gg1 = tanh_(pg1 + d1g + bg1);
        float o1 = sig_(po1 + d1o + bo1);
        cst1 = f1 * cst1 + i1 * gg1;
        float hv1 = o1 * tanh_(cst1);

        if (t == 255) {
            out[320 + b * 512 + h_0]         = hv0;
            out[320 + 32768 + b * 512 + h_0] = cst0;
            out[320 + b * 512 + h_1]         = hv1;
            out[320 + 32768 + b * 512 + h_1] = cst1;
        } else {
            __nv_bfloat16 h0h = __float2bfloat16(hv0);
            __nv_bfloat16 h0l = __float2bfloat16(hv0 - __bfloat162float(h0h));
            __nv_bfloat16 h1h = __float2bfloat16(hv1);
            __nv_bfloat16 h1l = __float2bfloat16(hv1 - __bfloat162float(h1h));
            const int nb = (t + 1) & 1;
            g_hh[nb][b * 512 + h_0] = h0h;  g_hl[nb][b * 512 + h_0] = h0l;
            g_hh[nb][b * 512 + h_1] = h1h;  g_hl[nb][b * 512 + h_1] = h1l;
            __syncthreads();                 // order h stores before arrival
            if (tid == 0) bar_arrive_release(&g_bar);
        }
    }
}

__global__ void __launch_bounds__(128, 2) fused_kernel(
    const float* __restrict__ Wfh, const float* __restrict__ Wih,
    const float* __restrict__ Wgh, const float* __restrict__ Woh,
    const float* __restrict__ Bf,  const float* __restrict__ Bi,
    const float* __restrict__ Bg,  const float* __restrict__ Bo,
    float* __restrict__ out)
{
    extern __shared__ char smem[];
    if (blockIdx.x < 128) {
        lstm_role(smem, Wfh, Wih, Wgh, Woh, Bf, Bi, Bg, Bo, out);
    } else {
        gemm_role((int)blockIdx.x - 128, smem);
    }
}

// ======================= Phase 3: output head ================================
__global__ void head_kernel(const float* __restrict__ Wl, const float* __restrict__ bl,
                            float* __restrict__ out)
{
    int b = blockIdx.x;
    int tid = threadIdx.x;
    int o = tid >> 5, lane = tid & 31;
    const float* hrow = out + 320 + b * 512;
    float s = 0.0f;
#pragma unroll 4
    for (int k = lane; k < 512; k += 32) s += hrow[k] * Wl[k * 5 + o];
#pragma unroll
    for (int m = 16; m; m >>= 1) s += __shfl_xor_sync(0xffffffffu, s, m);
    if (lane == 0) out[b * 5 + o] = s + bl[o];
}

// ======================= launch =============================================
extern "C" void kernel_launch(void* const* d_in, const int* in_sizes, int n_in,
                              void* d_out, int out_size)
{
    const int*   x   = (const int*)d_in[0];
    const float* emb = (const float*)d_in[1];
    const float* Wfx = (const float*)d_in[2];
    const float* Wfh = (const float*)d_in[3];
    const float* bf  = (const float*)d_in[4];
    const float* Wix = (const float*)d_in[5];
    const float* Wih = (const float*)d_in[6];
    const float* bi  = (const float*)d_in[7];
    const float* Wgx = (const float*)d_in[8];
    const float* Wgh = (const float*)d_in[9];
    const float* bg  = (const float*)d_in[10];
    const float* Wox = (const float*)d_in[11];
    const float* Woh = (const float*)d_in[12];
    const float* bo  = (const float*)d_in[13];
    const float* Wl  = (const float*)d_in[14];
    const float* bl  = (const float*)d_in[15];
    float* out = (float*)d_out;

    cudaFuncSetAttribute(fused_kernel, cudaFuncAttributeMaxDynamicSharedMemorySize, 98304);

    prep_kernel<<<1, 256>>>();
    prep_w_kernel<<<4 * 16 * 128, 256>>>(Wfx, Wix, Wgx, Wox);
    prep_a_kernel<<<16384, 128>>>(x, emb);
    fused_kernel<<<4224, 128, 98304>>>(Wfh, Wih, Wgh, Woh, bf, bi, bg, bo, out);
    head_kernel<<<64, 160>>>(Wl, bl, out);
}